// round 7
// baseline (speedup 1.0000x reference)
#include <cuda_runtime.h>
#include <cstdint>

#define NNODE 50000
#define NEDGE 800000
#define DIM 128
#define NGRAPH 100
#define NEG_SLOPE 0.01f

// ---------------- scratch (device globals; no allocations, no host API needed) --------
__device__ float g_h [NNODE*DIM];   // lrelu(node_feats @ Wn + bn)
__device__ float g_u [NNODE*DIM];   // lrelu(graph_feats @ Wg + bg)
__device__ float g_A [NNODE*DIM];   // h @ Weu[0:128]
__device__ float g_BC[NNODE*DIM];   // h @ Weu[128:256] + u @ Weu[384:512] + beu
__device__ float g_P [NNODE*DIM];   // h @ Wnu[0:128] + u @ Wnu[256:384] + bnu
__device__ float g_hf[NNODE*DIM];   // segment_sum(f_new, dst)
__device__ float g_deg[NNODE];      // in-degree
__device__ float g_poolN[NGRAPH*DIM];
__device__ float g_poolE[NGRAPH*DIM];
__device__ float g_poolG[NGRAPH*DIM];
__device__ float g_cntN[NGRAPH];
__device__ float g_cntE[NGRAPH];
__device__ float g_gnew[NGRAPH*DIM];

__device__ __forceinline__ float lrelu(float x) { return x > 0.0f ? x : NEG_SLOPE * x; }

// ---------------- zero scratch accumulators ----------------
__global__ void zero_kernel()
{
    int i = blockIdx.x * blockDim.x + threadIdx.x;
    int stride = gridDim.x * blockDim.x;
    for (int k = i; k < NNODE*DIM; k += stride) g_hf[k] = 0.0f;
    for (int k = i; k < NNODE; k += stride) g_deg[k] = 0.0f;
    for (int k = i; k < NGRAPH*DIM; k += stride) { g_poolN[k]=0.f; g_poolE[k]=0.f; g_poolG[k]=0.f; }
    for (int k = i; k < NGRAPH; k += stride) { g_cntN[k]=0.f; g_cntE[k]=0.f; }
}

// ============================================================================
// Core streamed 128x128-tile GEMM (K=N=128), 256 threads, 8x8 microtile.
// out[row] = act?( X0@W0 [+ X1@W1] [+ bias] ). Static SMEM ~16.5-33KB.
// ============================================================================
template<bool TWO, bool ACT, bool HASBIAS>
__device__ __forceinline__ void gemm128_core(
    const float* __restrict__ X0, const float* __restrict__ W0,
    const float* __restrict__ X1, const float* __restrict__ W1,
    const float* __restrict__ bias, float* __restrict__ out, int M)
{
    __shared__ float As0[16][132];
    __shared__ float Bs0[16][128];
    __shared__ float As1[TWO ? 16 : 1][TWO ? 132 : 1];
    __shared__ float Bs1[TWO ? 16 : 1][TWO ? 128 : 1];

    const int tid = threadIdx.x;
    const int tx = tid & 15, ty = tid >> 4;
    const int m0 = blockIdx.x * 128;

    const int lr  = tid >> 2;
    const int lk  = (tid & 3) * 4;
    const int bn4 = (tid & 31) * 4;
    const int bk  = tid >> 5;

    float acc[8][8];
    #pragma unroll
    for (int i = 0; i < 8; i++)
        #pragma unroll
        for (int j = 0; j < 8; j++) acc[i][j] = 0.0f;

    for (int k0 = 0; k0 < DIM; k0 += 16) {
        #pragma unroll
        for (int it = 0; it < 2; it++) {
            int rr = lr + it*64;
            int row = min(m0 + rr, M - 1);
            float4 v = *(const float4*)(X0 + (size_t)row*DIM + k0 + lk);
            As0[lk+0][rr]=v.x; As0[lk+1][rr]=v.y; As0[lk+2][rr]=v.z; As0[lk+3][rr]=v.w;
            if (TWO) {
                float4 w = *(const float4*)(X1 + (size_t)row*DIM + k0 + lk);
                As1[lk+0][rr]=w.x; As1[lk+1][rr]=w.y; As1[lk+2][rr]=w.z; As1[lk+3][rr]=w.w;
            }
        }
        #pragma unroll
        for (int it = 0; it < 2; it++) {
            int kr = bk + it*8;
            *(float4*)&Bs0[kr][bn4] = *(const float4*)(W0 + (size_t)(k0+kr)*DIM + bn4);
            if (TWO)
                *(float4*)&Bs1[kr][bn4] = *(const float4*)(W1 + (size_t)(k0+kr)*DIM + bn4);
        }
        __syncthreads();
        #pragma unroll
        for (int kk = 0; kk < 16; kk++) {
            float a[8], b[8];
            *(float4*)(a)   = *(float4*)&As0[kk][ty*8];
            *(float4*)(a+4) = *(float4*)&As0[kk][ty*8+4];
            *(float4*)(b)   = *(float4*)&Bs0[kk][tx*8];
            *(float4*)(b+4) = *(float4*)&Bs0[kk][tx*8+4];
            #pragma unroll
            for (int i = 0; i < 8; i++)
                #pragma unroll
                for (int j = 0; j < 8; j++) acc[i][j] += a[i]*b[j];
            if (TWO) {
                *(float4*)(a)   = *(float4*)&As1[kk][ty*8];
                *(float4*)(a+4) = *(float4*)&As1[kk][ty*8+4];
                *(float4*)(b)   = *(float4*)&Bs1[kk][tx*8];
                *(float4*)(b+4) = *(float4*)&Bs1[kk][tx*8+4];
                #pragma unroll
                for (int i = 0; i < 8; i++)
                    #pragma unroll
                    for (int j = 0; j < 8; j++) acc[i][j] += a[i]*b[j];
            }
        }
        __syncthreads();
    }

    float bv[8];
    if (HASBIAS) {
        *(float4*)(bv)   = *(const float4*)(bias + tx*8);
        *(float4*)(bv+4) = *(const float4*)(bias + tx*8 + 4);
    } else {
        #pragma unroll
        for (int j = 0; j < 8; j++) bv[j] = 0.0f;
    }

    #pragma unroll
    for (int i = 0; i < 8; i++) {
        int row = m0 + ty*8 + i;
        if (row >= M) continue;
        #pragma unroll
        for (int j4 = 0; j4 < 8; j4 += 4) {
            float v0 = acc[i][j4+0] + bv[j4+0];
            float v1 = acc[i][j4+1] + bv[j4+1];
            float v2 = acc[i][j4+2] + bv[j4+2];
            float v3 = acc[i][j4+3] + bv[j4+3];
            if (ACT) { v0 = lrelu(v0); v1 = lrelu(v1); v2 = lrelu(v2); v3 = lrelu(v3); }
            *(float4*)(out + (size_t)row*DIM + tx*8 + j4) = make_float4(v0, v1, v2, v3);
        }
    }
}

// ---- node-side GEMM wrappers (globals referenced device-side; no symbol API) ----
__global__ __launch_bounds__(256) void k_proj_h(const float* __restrict__ NF,
                                                const float* __restrict__ Wn,
                                                const float* __restrict__ bn)
{ gemm128_core<false, true, true>(NF, Wn, nullptr, nullptr, bn, g_h, NNODE); }

__global__ __launch_bounds__(256) void k_proj_u(const float* __restrict__ GF,
                                                const float* __restrict__ Wg,
                                                const float* __restrict__ bg)
{ gemm128_core<false, true, true>(GF, Wg, nullptr, nullptr, bg, g_u, NNODE); }

__global__ __launch_bounds__(256) void k_pre_A(const float* __restrict__ Weu0)
{ gemm128_core<false, false, false>(g_h, Weu0, nullptr, nullptr, nullptr, g_A, NNODE); }

__global__ __launch_bounds__(256) void k_pre_BC(const float* __restrict__ Weu1,
                                                const float* __restrict__ Weu3,
                                                const float* __restrict__ beu)
{ gemm128_core<true, false, true>(g_h, Weu1, g_u, Weu3, beu, g_BC, NNODE); }

__global__ __launch_bounds__(256) void k_pre_P(const float* __restrict__ Wnu0,
                                               const float* __restrict__ Wnu2,
                                               const float* __restrict__ bnu)
{ gemm128_core<true, false, true>(g_h, Wnu0, g_u, Wnu2, bnu, g_P, NNODE); }

// ============================================================================
// Edge stage 1: f = lrelu(EF @ We + be) -> staged into out2 (scratch use of d_out).
// Also accumulates in-degree.
// ============================================================================
__global__ __launch_bounds__(256) void edge_gemm1_kernel(
    const float* __restrict__ EF,
    const int* __restrict__ dst,
    const float* __restrict__ We,
    const float* __restrict__ be,
    float* __restrict__ out2)
{
    if (threadIdx.x < 128)
        atomicAdd(&g_deg[dst[blockIdx.x * 128 + threadIdx.x]], 1.0f);
    gemm128_core<false, true, true>(EF, We, nullptr, nullptr, be, out2, NEDGE);
}

// ============================================================================
// Edge stage 2: t = f @ Weu2 (f read from out2); f_new = lrelu(t + A[src] + BC[dst]);
// out2 = f_new + EF (overwrites f); atomic g_hf[dst] += f_new.
// Each block reads only its own 128 rows of out2 before overwriting -> race-free.
// ============================================================================
__global__ __launch_bounds__(256) void edge_gemm2_kernel(
    const float* __restrict__ EF,
    const int* __restrict__ src,
    const int* __restrict__ dst,
    const float* __restrict__ Weu2,
    float* __restrict__ out2)
{
    __shared__ float As[16][132];
    __shared__ float Bs[16][128];
    __shared__ int ssrc[128];
    __shared__ int sdst[128];

    const int tid = threadIdx.x;
    const int tx = tid & 15, ty = tid >> 4;
    const int m0 = blockIdx.x * 128;

    if (tid < 128) {
        ssrc[tid] = src[m0 + tid];
        sdst[tid] = dst[m0 + tid];
    }

    const int lr  = tid >> 2;
    const int lk  = (tid & 3) * 4;
    const int bn4 = (tid & 31) * 4;
    const int bk  = tid >> 5;

    float acc[8][8];
    #pragma unroll
    for (int i = 0; i < 8; i++)
        #pragma unroll
        for (int j = 0; j < 8; j++) acc[i][j] = 0.0f;

    for (int k0 = 0; k0 < DIM; k0 += 16) {
        #pragma unroll
        for (int it = 0; it < 2; it++) {
            int rr = lr + it*64;
            float4 v = *(const float4*)(out2 + (size_t)(m0 + rr)*DIM + k0 + lk);
            As[lk+0][rr]=v.x; As[lk+1][rr]=v.y; As[lk+2][rr]=v.z; As[lk+3][rr]=v.w;
        }
        #pragma unroll
        for (int it = 0; it < 2; it++) {
            int kr = bk + it*8;
            *(float4*)&Bs[kr][bn4] = *(const float4*)(Weu2 + (size_t)(k0+kr)*DIM + bn4);
        }
        __syncthreads();
        #pragma unroll
        for (int kk = 0; kk < 16; kk++) {
            float a[8], b[8];
            *(float4*)(a)   = *(float4*)&As[kk][ty*8];
            *(float4*)(a+4) = *(float4*)&As[kk][ty*8+4];
            *(float4*)(b)   = *(float4*)&Bs[kk][tx*8];
            *(float4*)(b+4) = *(float4*)&Bs[kk][tx*8+4];
            #pragma unroll
            for (int i = 0; i < 8; i++)
                #pragma unroll
                for (int j = 0; j < 8; j++) acc[i][j] += a[i]*b[j];
        }
        __syncthreads();
    }

    // epilogue: gather + lrelu + residual + atomic scatter
    #pragma unroll
    for (int i = 0; i < 8; i++) {
        int r = ty*8 + i;
        int e = m0 + r;
        int s  = ssrc[r], d2 = sdst[r];
        const float* Ar  = g_A  + (size_t)s *DIM + tx*8;
        const float* BCr = g_BC + (size_t)d2*DIM + tx*8;
        const float* Er  = EF   + (size_t)e *DIM + tx*8;
        float*       Hr  = g_hf + (size_t)d2*DIM + tx*8;
        float*       Or  = out2 + (size_t)e *DIM + tx*8;
        #pragma unroll
        for (int j4 = 0; j4 < 8; j4 += 4) {
            float4 a4  = *(const float4*)(Ar + j4);
            float4 bc4 = *(const float4*)(BCr + j4);
            float4 e4  = *(const float4*)(Er + j4);
            float f0 = lrelu(acc[i][j4+0] + a4.x + bc4.x);
            float f1 = lrelu(acc[i][j4+1] + a4.y + bc4.y);
            float f2 = lrelu(acc[i][j4+2] + a4.z + bc4.z);
            float f3 = lrelu(acc[i][j4+3] + a4.w + bc4.w);
            *(float4*)(Or + j4) = make_float4(f0+e4.x, f1+e4.y, f2+e4.z, f3+e4.w);
            atomicAdd(Hr + j4 + 0, f0);
            atomicAdd(Hr + j4 + 1, f1);
            atomicAdd(Hr + j4 + 2, f2);
            atomicAdd(Hr + j4 + 3, f3);
        }
    }
}

// ============================================================================
// Node update: node_new = lrelu(P + (hf/deg) @ Wnu1); out1 = node_new + NF;
// accumulates node pool (run-length aggregated atomics; node2graph sorted).
// ============================================================================
__global__ __launch_bounds__(256) void nodeupd_kernel(
    const float* __restrict__ NF,
    const int* __restrict__ n2g,
    const float* __restrict__ Wnu1,
    float* __restrict__ out1)
{
    __shared__ float As[16][132];
    __shared__ float Bs[16][128];
    __shared__ float sinv[128];
    __shared__ int   sg[128];

    const int tid = threadIdx.x;
    const int tx = tid & 15, ty = tid >> 4;
    const int m0 = blockIdx.x * 128;

    if (tid < 128) {
        int r = min(m0 + tid, NNODE - 1);
        sinv[tid] = 1.0f / fmaxf(g_deg[r], 1.0f);
        sg[tid]   = n2g[r];
    }
    __syncthreads();

    const int lr  = tid >> 2;
    const int lk  = (tid & 3) * 4;
    const int bn4 = (tid & 31) * 4;
    const int bk  = tid >> 5;

    float acc[8][8];
    #pragma unroll
    for (int i = 0; i < 8; i++)
        #pragma unroll
        for (int j = 0; j < 8; j++) acc[i][j] = 0.0f;

    for (int k0 = 0; k0 < DIM; k0 += 16) {
        #pragma unroll
        for (int it = 0; it < 2; it++) {
            int rr = lr + it*64;
            int row = min(m0 + rr, NNODE - 1);
            float sc = sinv[rr];
            float4 v = *(const float4*)(g_hf + (size_t)row*DIM + k0 + lk);
            As[lk+0][rr]=v.x*sc; As[lk+1][rr]=v.y*sc; As[lk+2][rr]=v.z*sc; As[lk+3][rr]=v.w*sc;
        }
        #pragma unroll
        for (int it = 0; it < 2; it++) {
            int kr = bk + it*8;
            *(float4*)&Bs[kr][bn4] = *(const float4*)(Wnu1 + (size_t)(k0+kr)*DIM + bn4);
        }
        __syncthreads();
        #pragma unroll
        for (int kk = 0; kk < 16; kk++) {
            float a[8], b[8];
            *(float4*)(a)   = *(float4*)&As[kk][ty*8];
            *(float4*)(a+4) = *(float4*)&As[kk][ty*8+4];
            *(float4*)(b)   = *(float4*)&Bs[kk][tx*8];
            *(float4*)(b+4) = *(float4*)&Bs[kk][tx*8+4];
            #pragma unroll
            for (int i = 0; i < 8; i++)
                #pragma unroll
                for (int j = 0; j < 8; j++) acc[i][j] += a[i]*b[j];
        }
        __syncthreads();
    }

    #pragma unroll
    for (int i = 0; i < 8; i++) {
        int row = m0 + ty*8 + i;
        int rc = min(row, NNODE - 1);
        const float* Pr = g_P + (size_t)rc*DIM + tx*8;
        const float* Nr = NF  + (size_t)rc*DIM + tx*8;
        #pragma unroll
        for (int j4 = 0; j4 < 8; j4 += 4) {
            float4 p4 = *(const float4*)(Pr + j4);
            float4 n4 = *(const float4*)(Nr + j4);
            acc[i][j4+0] = lrelu(acc[i][j4+0] + p4.x);
            acc[i][j4+1] = lrelu(acc[i][j4+1] + p4.y);
            acc[i][j4+2] = lrelu(acc[i][j4+2] + p4.z);
            acc[i][j4+3] = lrelu(acc[i][j4+3] + p4.w);
            if (row < NNODE) {
                *(float4*)(out1 + (size_t)row*DIM + tx*8 + j4) =
                    make_float4(acc[i][j4+0]+n4.x, acc[i][j4+1]+n4.y,
                                acc[i][j4+2]+n4.z, acc[i][j4+3]+n4.w);
            }
        }
    }

    #pragma unroll
    for (int j = 0; j < 8; j++) {
        float run = 0.0f;
        int curg = sg[ty*8];
        #pragma unroll
        for (int i = 0; i < 8; i++) {
            int row = m0 + ty*8 + i;
            int gg = sg[ty*8 + i];
            if (gg != curg) {
                atomicAdd(&g_poolN[curg*DIM + tx*8 + j], run);
                run = 0.0f; curg = gg;
            }
            if (row < NNODE) run += acc[i][j];
        }
        atomicAdd(&g_poolN[curg*DIM + tx*8 + j], run);
    }
}

// ---------------- pools over nodes: edge_pool(=seg hf), graph_pool, counts ----------------
__global__ void pool_kernel(const float* __restrict__ GF, const int* __restrict__ n2g)
{
    const int c  = threadIdx.x;           // 0..127 column
    const int r0 = blockIdx.x * 32;
    float accE = 0.0f, accG = 0.0f, ccN = 0.0f, ccE = 0.0f;
    int curg = -1;
    int rend = min(r0 + 32, NNODE);
    for (int r = r0; r < rend; r++) {
        int gg = n2g[r];
        if (gg != curg) {
            if (curg >= 0) {
                atomicAdd(&g_poolE[curg*DIM + c], accE);
                atomicAdd(&g_poolG[curg*DIM + c], accG);
                if (c == 0) { atomicAdd(&g_cntN[curg], ccN); atomicAdd(&g_cntE[curg], ccE); }
            }
            accE = accG = ccN = ccE = 0.0f;
            curg = gg;
        }
        accE += g_hf[(size_t)r*DIM + c];
        accG += GF  [(size_t)r*DIM + c];
        if (c == 0) { ccN += 1.0f; ccE += g_deg[r]; }
    }
    if (curg >= 0) {
        atomicAdd(&g_poolE[curg*DIM + c], accE);
        atomicAdd(&g_poolG[curg*DIM + c], accG);
        if (c == 0) { atomicAdd(&g_cntN[curg], ccN); atomicAdd(&g_cntE[curg], ccE); }
    }
}

// ---------------- graph update: g_new = lrelu(concat[pools] @ Wnu + bnu) ----------------
__global__ void graph_kernel(const float* __restrict__ Wnu, const float* __restrict__ bnu)
{
    __shared__ float sc[384];
    const int g = blockIdx.x;
    const int c = threadIdx.x;  // 128 threads
    float nn = fmaxf(g_cntN[g], 1.0f);
    float ne = fmaxf(g_cntE[g], 1.0f);
    sc[c]       = g_poolN[g*DIM + c] / nn;
    sc[128 + c] = g_poolE[g*DIM + c] / ne;
    sc[256 + c] = g_poolG[g*DIM + c] / nn;
    __syncthreads();
    float acc = bnu[c];
    #pragma unroll 8
    for (int k = 0; k < 384; k++) acc += sc[k] * Wnu[(size_t)k*DIM + c];
    g_gnew[g*DIM + c] = lrelu(acc);
}

// ---------------- out3 = g_new[node2graph] + graph_feats ----------------
__global__ void out3_kernel(const float* __restrict__ GF, const int* __restrict__ n2g,
                            float* __restrict__ out3)
{
    int idx = blockIdx.x * blockDim.x + threadIdx.x;  // over NNODE*32 float4s
    if (idx >= NNODE * 32) return;
    int node = idx >> 5;
    int c4 = (idx & 31) * 4;
    float4 gv = *(const float4*)(g_gnew + (size_t)n2g[node]*DIM + c4);
    float4 gf = *(const float4*)(GF + (size_t)node*DIM + c4);
    *(float4*)(out3 + (size_t)node*DIM + c4) =
        make_float4(gv.x+gf.x, gv.y+gf.y, gv.z+gf.z, gv.w+gf.w);
}

// ---------------- launch: pure kernel launches, no host CUDA API calls ----------------
extern "C" void kernel_launch(void* const* d_in, const int* in_sizes, int n_in,
                              void* d_out, int out_size)
{
    const float* node_feats  = (const float*)d_in[0];
    const float* edge_feats  = (const float*)d_in[1];
    const float* graph_feats = (const float*)d_in[2];
    const int*   src = (const int*)d_in[3];
    const int*   dst = (const int*)d_in[4];
    const int*   n2g = (const int*)d_in[5];
    const float* Wn  = (const float*)d_in[6];
    const float* bn  = (const float*)d_in[7];
    const float* We  = (const float*)d_in[8];
    const float* be  = (const float*)d_in[9];
    const float* Wg  = (const float*)d_in[10];
    const float* bg  = (const float*)d_in[11];
    const float* Weu = (const float*)d_in[12];
    const float* beu = (const float*)d_in[13];
    const float* Wnu = (const float*)d_in[14];
    const float* bnu = (const float*)d_in[15];

    float* out  = (float*)d_out;
    float* out1 = out;                                            // [N,D] node
    float* out2 = out + (size_t)NNODE*DIM;                        // [E,D] edge (also f scratch)
    float* out3 = out + (size_t)NNODE*DIM + (size_t)NEDGE*DIM;    // [N,D] graph-bcast

    const int gn = (NNODE + 127) / 128;
    const int ge = NEDGE / 128;

    zero_kernel<<<512, 256>>>();
    // projections
    k_proj_h<<<gn, 256>>>(node_feats, Wn, bn);
    k_proj_u<<<gn, 256>>>(graph_feats, Wg, bg);
    // per-node precomputations for edge / node updates
    k_pre_A <<<gn, 256>>>(Weu);
    k_pre_BC<<<gn, 256>>>(Weu + 128*DIM, Weu + 384*DIM, beu);
    k_pre_P <<<gn, 256>>>(Wnu, Wnu + 256*DIM, bnu);
    // edge pipeline (f staged in out2)
    edge_gemm1_kernel<<<ge, 256>>>(edge_feats, dst, We, be, out2);
    edge_gemm2_kernel<<<ge, 256>>>(edge_feats, src, dst, Weu + 256*DIM, out2);
    // pooling pieces + node update
    pool_kernel<<<(NNODE + 31)/32, 128>>>(graph_feats, n2g);
    nodeupd_kernel<<<gn, 256>>>(node_feats, n2g, Wnu + 128*DIM, out1);
    // graph update + broadcast
    graph_kernel<<<NGRAPH, 128>>>(Wnu, bnu);
    out3_kernel<<<(NNODE*32 + 255)/256, 256>>>(graph_feats, n2g, out3);
}

// round 9
// speedup vs baseline: 1.0314x; 1.0314x over previous
#include <cuda_runtime.h>
#include <cstdint>

#define NNODE 50000
#define NEDGE 800000
#define DIM 128
#define NGRAPH 100
#define NEG_SLOPE 0.01f

// ---------------- scratch (device globals) ----------------
__device__ float g_h [NNODE*DIM];
__device__ float g_u [NNODE*DIM];
__device__ float g_A [NNODE*DIM];
__device__ float g_BC[NNODE*DIM];
__device__ float g_P [NNODE*DIM];
__device__ float g_hf[NNODE*DIM];
__device__ float g_deg[NNODE];
__device__ float g_poolN[NGRAPH*DIM];
__device__ float g_poolE[NGRAPH*DIM];
__device__ float g_poolG[NGRAPH*DIM];
__device__ float g_cntN[NGRAPH];
__device__ float g_cntE[NGRAPH];
__device__ float g_gnew[NGRAPH*DIM];

__device__ __forceinline__ float lrelu(float x) { return x > 0.0f ? x : NEG_SLOPE * x; }

// ---------------- packed fp32x2 helpers (Blackwell FFMA2) ----------------
__device__ __forceinline__ void ffma2(unsigned long long& d,
                                      unsigned long long a,
                                      unsigned long long b)
{
    asm("fma.rn.f32x2 %0, %1, %2, %3;" : "=l"(d) : "l"(a), "l"(b), "l"(d));
}
__device__ __forceinline__ unsigned long long splat2(float x)
{
    unsigned long long r;
    asm("mov.b64 %0, {%1, %1};" : "=l"(r) : "f"(x));
    return r;
}
__device__ __forceinline__ float2 unpack2(unsigned long long v)
{
    float2 r;
    asm("mov.b64 {%0, %1}, %2;" : "=f"(r.x), "=f"(r.y) : "l"(v));
    return r;
}

// ---------------- zero scratch accumulators ----------------
__global__ void zero_kernel()
{
    int i = blockIdx.x * blockDim.x + threadIdx.x;
    int stride = gridDim.x * blockDim.x;
    for (int k = i; k < NNODE*DIM; k += stride) g_hf[k] = 0.0f;
    for (int k = i; k < NNODE; k += stride) g_deg[k] = 0.0f;
    for (int k = i; k < NGRAPH*DIM; k += stride) { g_poolN[k]=0.f; g_poolE[k]=0.f; g_poolG[k]=0.f; }
    for (int k = i; k < NGRAPH; k += stride) { g_cntN[k]=0.f; g_cntE[k]=0.f; }
}

// ============================================================================
// Core streamed 128x128-tile GEMM (K=N=128), 256 threads, 8x8 microtile,
// packed f32x2 accumulation: acc2[i][jj] holds output cols {2jj, 2jj+1}.
// ============================================================================
template<bool TWO, bool ACT, bool HASBIAS>
__device__ __forceinline__ void gemm128_core(
    const float* __restrict__ X0, const float* __restrict__ W0,
    const float* __restrict__ X1, const float* __restrict__ W1,
    const float* __restrict__ bias, float* __restrict__ out, int M)
{
    __shared__ __align__(16) float As0[16][132];
    __shared__ __align__(16) float Bs0[16][128];
    __shared__ __align__(16) float As1[TWO ? 16 : 1][TWO ? 132 : 1];
    __shared__ __align__(16) float Bs1[TWO ? 16 : 1][TWO ? 128 : 1];

    const int tid = threadIdx.x;
    const int tx = tid & 15, ty = tid >> 4;
    const int m0 = blockIdx.x * 128;

    const int lr  = tid >> 2;
    const int lk  = (tid & 3) * 4;
    const int bn4 = (tid & 31) * 4;
    const int bk  = tid >> 5;

    unsigned long long acc2[8][4];
    #pragma unroll
    for (int i = 0; i < 8; i++)
        #pragma unroll
        for (int j = 0; j < 4; j++) acc2[i][j] = 0ULL;

    for (int k0 = 0; k0 < DIM; k0 += 16) {
        #pragma unroll
        for (int it = 0; it < 2; it++) {
            int rr = lr + it*64;
            int row = min(m0 + rr, M - 1);
            float4 v = *(const float4*)(X0 + (size_t)row*DIM + k0 + lk);
            As0[lk+0][rr]=v.x; As0[lk+1][rr]=v.y; As0[lk+2][rr]=v.z; As0[lk+3][rr]=v.w;
            if (TWO) {
                float4 w = *(const float4*)(X1 + (size_t)row*DIM + k0 + lk);
                As1[lk+0][rr]=w.x; As1[lk+1][rr]=w.y; As1[lk+2][rr]=w.z; As1[lk+3][rr]=w.w;
            }
        }
        #pragma unroll
        for (int it = 0; it < 2; it++) {
            int kr = bk + it*8;
            *(float4*)&Bs0[kr][bn4] = *(const float4*)(W0 + (size_t)(k0+kr)*DIM + bn4);
            if (TWO)
                *(float4*)&Bs1[kr][bn4] = *(const float4*)(W1 + (size_t)(k0+kr)*DIM + bn4);
        }
        __syncthreads();
        #pragma unroll
        for (int kk = 0; kk < 16; kk++) {
            {
                float a[8];
                *(float4*)(a)   = *(float4*)&As0[kk][ty*8];
                *(float4*)(a+4) = *(float4*)&As0[kk][ty*8+4];
                ulonglong2 bA = *(ulonglong2*)&Bs0[kk][tx*8];
                ulonglong2 bB = *(ulonglong2*)&Bs0[kk][tx*8+4];
                unsigned long long b2[4] = {bA.x, bA.y, bB.x, bB.y};
                #pragma unroll
                for (int i = 0; i < 8; i++) {
                    unsigned long long a2 = splat2(a[i]);
                    ffma2(acc2[i][0], a2, b2[0]);
                    ffma2(acc2[i][1], a2, b2[1]);
                    ffma2(acc2[i][2], a2, b2[2]);
                    ffma2(acc2[i][3], a2, b2[3]);
                }
            }
            if (TWO) {
                float a[8];
                *(float4*)(a)   = *(float4*)&As1[kk][ty*8];
                *(float4*)(a+4) = *(float4*)&As1[kk][ty*8+4];
                ulonglong2 bA = *(ulonglong2*)&Bs1[kk][tx*8];
                ulonglong2 bB = *(ulonglong2*)&Bs1[kk][tx*8+4];
                unsigned long long b2[4] = {bA.x, bA.y, bB.x, bB.y};
                #pragma unroll
                for (int i = 0; i < 8; i++) {
                    unsigned long long a2 = splat2(a[i]);
                    ffma2(acc2[i][0], a2, b2[0]);
                    ffma2(acc2[i][1], a2, b2[1]);
                    ffma2(acc2[i][2], a2, b2[2]);
                    ffma2(acc2[i][3], a2, b2[3]);
                }
            }
        }
        __syncthreads();
    }

    float bv[8];
    if (HASBIAS) {
        *(float4*)(bv)   = *(const float4*)(bias + tx*8);
        *(float4*)(bv+4) = *(const float4*)(bias + tx*8 + 4);
    } else {
        #pragma unroll
        for (int j = 0; j < 8; j++) bv[j] = 0.0f;
    }

    #pragma unroll
    for (int i = 0; i < 8; i++) {
        int row = m0 + ty*8 + i;
        if (row >= M) continue;
        #pragma unroll
        for (int j4 = 0; j4 < 8; j4 += 4) {
            float2 p0 = unpack2(acc2[i][j4/2]);
            float2 p1 = unpack2(acc2[i][j4/2 + 1]);
            float v0 = p0.x + bv[j4+0];
            float v1 = p0.y + bv[j4+1];
            float v2 = p1.x + bv[j4+2];
            float v3 = p1.y + bv[j4+3];
            if (ACT) { v0 = lrelu(v0); v1 = lrelu(v1); v2 = lrelu(v2); v3 = lrelu(v3); }
            *(float4*)(out + (size_t)row*DIM + tx*8 + j4) = make_float4(v0, v1, v2, v3);
        }
    }
}

// ---- node-side GEMM wrappers ----
__global__ __launch_bounds__(256) void k_proj_h(const float* __restrict__ NF,
                                                const float* __restrict__ Wn,
                                                const float* __restrict__ bn)
{ gemm128_core<false, true, true>(NF, Wn, nullptr, nullptr, bn, g_h, NNODE); }

__global__ __launch_bounds__(256) void k_proj_u(const float* __restrict__ GF,
                                                const float* __restrict__ Wg,
                                                const float* __restrict__ bg)
{ gemm128_core<false, true, true>(GF, Wg, nullptr, nullptr, bg, g_u, NNODE); }

__global__ __launch_bounds__(256) void k_pre_A(const float* __restrict__ Weu0)
{ gemm128_core<false, false, false>(g_h, Weu0, nullptr, nullptr, nullptr, g_A, NNODE); }

__global__ __launch_bounds__(256) void k_pre_BC(const float* __restrict__ Weu1,
                                                const float* __restrict__ Weu3,
                                                const float* __restrict__ beu)
{ gemm128_core<true, false, true>(g_h, Weu1, g_u, Weu3, beu, g_BC, NNODE); }

__global__ __launch_bounds__(256) void k_pre_P(const float* __restrict__ Wnu0,
                                               const float* __restrict__ Wnu2,
                                               const float* __restrict__ bnu)
{ gemm128_core<true, false, true>(g_h, Wnu0, g_u, Wnu2, bnu, g_P, NNODE); }

// ============================================================================
// Edge stage 1: f = lrelu(EF @ We + be) -> staged into out2. Also in-degree.
// ============================================================================
__global__ __launch_bounds__(256) void edge_gemm1_kernel(
    const float* __restrict__ EF,
    const int* __restrict__ dst,
    const float* __restrict__ We,
    const float* __restrict__ be,
    float* __restrict__ out2)
{
    if (threadIdx.x < 128)
        atomicAdd(&g_deg[dst[blockIdx.x * 128 + threadIdx.x]], 1.0f);
    gemm128_core<false, true, true>(EF, We, nullptr, nullptr, be, out2, NEDGE);
}

// ============================================================================
// Edge stage 2: t = f @ Weu2 (f from out2); f_new = lrelu(t + A[src] + BC[dst]);
// out2 = f_new + EF (overwrite); atomic g_hf[dst] += f_new.
// ============================================================================
__global__ __launch_bounds__(256) void edge_gemm2_kernel(
    const float* __restrict__ EF,
    const int* __restrict__ src,
    const int* __restrict__ dst,
    const float* __restrict__ Weu2,
    float* __restrict__ out2)
{
    __shared__ __align__(16) float As[16][132];
    __shared__ __align__(16) float Bs[16][128];
    __shared__ int ssrc[128];
    __shared__ int sdst[128];

    const int tid = threadIdx.x;
    const int tx = tid & 15, ty = tid >> 4;
    const int m0 = blockIdx.x * 128;

    if (tid < 128) {
        ssrc[tid] = src[m0 + tid];
        sdst[tid] = dst[m0 + tid];
    }

    const int lr  = tid >> 2;
    const int lk  = (tid & 3) * 4;
    const int bn4 = (tid & 31) * 4;
    const int bk  = tid >> 5;

    unsigned long long acc2[8][4];
    #pragma unroll
    for (int i = 0; i < 8; i++)
        #pragma unroll
        for (int j = 0; j < 4; j++) acc2[i][j] = 0ULL;

    for (int k0 = 0; k0 < DIM; k0 += 16) {
        #pragma unroll
        for (int it = 0; it < 2; it++) {
            int rr = lr + it*64;
            float4 v = *(const float4*)(out2 + (size_t)(m0 + rr)*DIM + k0 + lk);
            As[lk+0][rr]=v.x; As[lk+1][rr]=v.y; As[lk+2][rr]=v.z; As[lk+3][rr]=v.w;
        }
        #pragma unroll
        for (int it = 0; it < 2; it++) {
            int kr = bk + it*8;
            *(float4*)&Bs[kr][bn4] = *(const float4*)(Weu2 + (size_t)(k0+kr)*DIM + bn4);
        }
        __syncthreads();
        #pragma unroll
        for (int kk = 0; kk < 16; kk++) {
            float a[8];
            *(float4*)(a)   = *(float4*)&As[kk][ty*8];
            *(float4*)(a+4) = *(float4*)&As[kk][ty*8+4];
            ulonglong2 bA = *(ulonglong2*)&Bs[kk][tx*8];
            ulonglong2 bB = *(ulonglong2*)&Bs[kk][tx*8+4];
            unsigned long long b2[4] = {bA.x, bA.y, bB.x, bB.y};
            #pragma unroll
            for (int i = 0; i < 8; i++) {
                unsigned long long a2 = splat2(a[i]);
                ffma2(acc2[i][0], a2, b2[0]);
                ffma2(acc2[i][1], a2, b2[1]);
                ffma2(acc2[i][2], a2, b2[2]);
                ffma2(acc2[i][3], a2, b2[3]);
            }
        }
        __syncthreads();
    }

    // epilogue: gather + lrelu + residual + atomic scatter
    #pragma unroll
    for (int i = 0; i < 8; i++) {
        int r = ty*8 + i;
        int e = m0 + r;
        int s  = ssrc[r], d2 = sdst[r];
        const float* Ar  = g_A  + (size_t)s *DIM + tx*8;
        const float* BCr = g_BC + (size_t)d2*DIM + tx*8;
        const float* Er  = EF   + (size_t)e *DIM + tx*8;
        float*       Hr  = g_hf + (size_t)d2*DIM + tx*8;
        float*       Or  = out2 + (size_t)e *DIM + tx*8;
        #pragma unroll
        for (int j4 = 0; j4 < 8; j4 += 4) {
            float2 p0 = unpack2(acc2[i][j4/2]);
            float2 p1 = unpack2(acc2[i][j4/2 + 1]);
            float4 a4  = *(const float4*)(Ar + j4);
            float4 bc4 = *(const float4*)(BCr + j4);
            float4 e4  = *(const float4*)(Er + j4);
            float f0 = lrelu(p0.x + a4.x + bc4.x);
            float f1 = lrelu(p0.y + a4.y + bc4.y);
            float f2 = lrelu(p1.x + a4.z + bc4.z);
            float f3 = lrelu(p1.y + a4.w + bc4.w);
            *(float4*)(Or + j4) = make_float4(f0+e4.x, f1+e4.y, f2+e4.z, f3+e4.w);
            atomicAdd(Hr + j4 + 0, f0);
            atomicAdd(Hr + j4 + 1, f1);
            atomicAdd(Hr + j4 + 2, f2);
            atomicAdd(Hr + j4 + 3, f3);
        }
    }
}

// ============================================================================
// Node update: node_new = lrelu(P + (hf/deg) @ Wnu1); out1 = node_new + NF;
// node pool via run-length aggregated atomics.
// ============================================================================
__global__ __launch_bounds__(256) void nodeupd_kernel(
    const float* __restrict__ NF,
    const int* __restrict__ n2g,
    const float* __restrict__ Wnu1,
    float* __restrict__ out1)
{
    __shared__ __align__(16) float As[16][132];
    __shared__ __align__(16) float Bs[16][128];
    __shared__ float sinv[128];
    __shared__ int   sg[128];

    const int tid = threadIdx.x;
    const int tx = tid & 15, ty = tid >> 4;
    const int m0 = blockIdx.x * 128;

    if (tid < 128) {
        int r = min(m0 + tid, NNODE - 1);
        sinv[tid] = 1.0f / fmaxf(g_deg[r], 1.0f);
        sg[tid]   = n2g[r];
    }
    __syncthreads();

    const int lr  = tid >> 2;
    const int lk  = (tid & 3) * 4;
    const int bn4 = (tid & 31) * 4;
    const int bk  = tid >> 5;

    unsigned long long acc2[8][4];
    #pragma unroll
    for (int i = 0; i < 8; i++)
        #pragma unroll
        for (int j = 0; j < 4; j++) acc2[i][j] = 0ULL;

    for (int k0 = 0; k0 < DIM; k0 += 16) {
        #pragma unroll
        for (int it = 0; it < 2; it++) {
            int rr = lr + it*64;
            int row = min(m0 + rr, NNODE - 1);
            float sc = sinv[rr];
            float4 v = *(const float4*)(g_hf + (size_t)row*DIM + k0 + lk);
            As[lk+0][rr]=v.x*sc; As[lk+1][rr]=v.y*sc; As[lk+2][rr]=v.z*sc; As[lk+3][rr]=v.w*sc;
        }
        #pragma unroll
        for (int it = 0; it < 2; it++) {
            int kr = bk + it*8;
            *(float4*)&Bs[kr][bn4] = *(const float4*)(Wnu1 + (size_t)(k0+kr)*DIM + bn4);
        }
        __syncthreads();
        #pragma unroll
        for (int kk = 0; kk < 16; kk++) {
            float a[8];
            *(float4*)(a)   = *(float4*)&As[kk][ty*8];
            *(float4*)(a+4) = *(float4*)&As[kk][ty*8+4];
            ulonglong2 bA = *(ulonglong2*)&Bs[kk][tx*8];
            ulonglong2 bB = *(ulonglong2*)&Bs[kk][tx*8+4];
            unsigned long long b2[4] = {bA.x, bA.y, bB.x, bB.y};
            #pragma unroll
            for (int i = 0; i < 8; i++) {
                unsigned long long a2 = splat2(a[i]);
                ffma2(acc2[i][0], a2, b2[0]);
                ffma2(acc2[i][1], a2, b2[1]);
                ffma2(acc2[i][2], a2, b2[2]);
                ffma2(acc2[i][3], a2, b2[3]);
            }
        }
        __syncthreads();
    }

    float accf[8][8];
    #pragma unroll
    for (int i = 0; i < 8; i++) {
        int row = m0 + ty*8 + i;
        int rc = min(row, NNODE - 1);
        const float* Pr = g_P + (size_t)rc*DIM + tx*8;
        const float* Nr = NF  + (size_t)rc*DIM + tx*8;
        #pragma unroll
        for (int j4 = 0; j4 < 8; j4 += 4) {
            float2 p0 = unpack2(acc2[i][j4/2]);
            float2 p1 = unpack2(acc2[i][j4/2 + 1]);
            float4 pp = *(const float4*)(Pr + j4);
            float4 n4 = *(const float4*)(Nr + j4);
            accf[i][j4+0] = lrelu(p0.x + pp.x);
            accf[i][j4+1] = lrelu(p0.y + pp.y);
            accf[i][j4+2] = lrelu(p1.x + pp.z);
            accf[i][j4+3] = lrelu(p1.y + pp.w);
            if (row < NNODE) {
                *(float4*)(out1 + (size_t)row*DIM + tx*8 + j4) =
                    make_float4(accf[i][j4+0]+n4.x, accf[i][j4+1]+n4.y,
                                accf[i][j4+2]+n4.z, accf[i][j4+3]+n4.w);
            }
        }
    }

    #pragma unroll
    for (int j = 0; j < 8; j++) {
        float run = 0.0f;
        int curg = sg[ty*8];
        #pragma unroll
        for (int i = 0; i < 8; i++) {
            int row = m0 + ty*8 + i;
            int gg = sg[ty*8 + i];
            if (gg != curg) {
                atomicAdd(&g_poolN[curg*DIM + tx*8 + j], run);
                run = 0.0f; curg = gg;
            }
            if (row < NNODE) run += accf[i][j];
        }
        atomicAdd(&g_poolN[curg*DIM + tx*8 + j], run);
    }
}

// ---------------- pools over nodes ----------------
__global__ void pool_kernel(const float* __restrict__ GF, const int* __restrict__ n2g)
{
    const int c  = threadIdx.x;
    const int r0 = blockIdx.x * 32;
    float accE = 0.0f, accG = 0.0f, ccN = 0.0f, ccE = 0.0f;
    int curg = -1;
    int rend = min(r0 + 32, NNODE);
    for (int r = r0; r < rend; r++) {
        int gg = n2g[r];
        if (gg != curg) {
            if (curg >= 0) {
                atomicAdd(&g_poolE[curg*DIM + c], accE);
                atomicAdd(&g_poolG[curg*DIM + c], accG);
                if (c == 0) { atomicAdd(&g_cntN[curg], ccN); atomicAdd(&g_cntE[curg], ccE); }
            }
            accE = accG = ccN = ccE = 0.0f;
            curg = gg;
        }
        accE += g_hf[(size_t)r*DIM + c];
        accG += GF  [(size_t)r*DIM + c];
        if (c == 0) { ccN += 1.0f; ccE += g_deg[r]; }
    }
    if (curg >= 0) {
        atomicAdd(&g_poolE[curg*DIM + c], accE);
        atomicAdd(&g_poolG[curg*DIM + c], accG);
        if (c == 0) { atomicAdd(&g_cntN[curg], ccN); atomicAdd(&g_cntE[curg], ccE); }
    }
}

// ---------------- graph update ----------------
__global__ void graph_kernel(const float* __restrict__ Wnu, const float* __restrict__ bnu)
{
    __shared__ float sc[384];
    const int g = blockIdx.x;
    const int c = threadIdx.x;
    float nn = fmaxf(g_cntN[g], 1.0f);
    float ne = fmaxf(g_cntE[g], 1.0f);
    sc[c]       = g_poolN[g*DIM + c] / nn;
    sc[128 + c] = g_poolE[g*DIM + c] / ne;
    sc[256 + c] = g_poolG[g*DIM + c] / nn;
    __syncthreads();
    float acc = bnu[c];
    #pragma unroll 8
    for (int k = 0; k < 384; k++) acc += sc[k] * Wnu[(size_t)k*DIM + c];
    g_gnew[g*DIM + c] = lrelu(acc);
}

// ---------------- out3 = g_new[node2graph] + graph_feats ----------------
__global__ void out3_kernel(const float* __restrict__ GF, const int* __restrict__ n2g,
                            float* __restrict__ out3)
{
    int idx = blockIdx.x * blockDim.x + threadIdx.x;
    if (idx >= NNODE * 32) return;
    int node = idx >> 5;
    int c4 = (idx & 31) * 4;
    float4 gv = *(const float4*)(g_gnew + (size_t)n2g[node]*DIM + c4);
    float4 gf = *(const float4*)(GF + (size_t)node*DIM + c4);
    *(float4*)(out3 + (size_t)node*DIM + c4) =
        make_float4(gv.x+gf.x, gv.y+gf.y, gv.z+gf.z, gv.w+gf.w);
}

// ---------------- launch: pure kernel launches ----------------
extern "C" void kernel_launch(void* const* d_in, const int* in_sizes, int n_in,
                              void* d_out, int out_size)
{
    const float* node_feats  = (const float*)d_in[0];
    const float* edge_feats  = (const float*)d_in[1];
    const float* graph_feats = (const float*)d_in[2];
    const int*   src = (const int*)d_in[3];
    const int*   dst = (const int*)d_in[4];
    const int*   n2g = (const int*)d_in[5];
    const float* Wn  = (const float*)d_in[6];
    const float* bn  = (const float*)d_in[7];
    const float* We  = (const float*)d_in[8];
    const float* be  = (const float*)d_in[9];
    const float* Wg  = (const float*)d_in[10];
    const float* bg  = (const float*)d_in[11];
    const float* Weu = (const float*)d_in[12];
    const float* beu = (const float*)d_in[13];
    const float* Wnu = (const float*)d_in[14];
    const float* bnu = (const float*)d_in[15];

    float* out  = (float*)d_out;
    float* out1 = out;
    float* out2 = out + (size_t)NNODE*DIM;
    float* out3 = out + (size_t)NNODE*DIM + (size_t)NEDGE*DIM;

    const int gn = (NNODE + 127) / 128;
    const int ge = NEDGE / 128;

    zero_kernel<<<512, 256>>>();
    // projections + per-node precomputations
    k_proj_h<<<gn, 256>>>(node_feats, Wn, bn);
    k_proj_u<<<gn, 256>>>(graph_feats, Wg, bg);
    k_pre_A <<<gn, 256>>>(Weu);
    k_pre_BC<<<gn, 256>>>(Weu + 128*DIM, Weu + 384*DIM, beu);
    k_pre_P <<<gn, 256>>>(Wnu, Wnu + 256*DIM, bnu);
    // edge pipeline (f staged in out2)
    edge_gemm1_kernel<<<ge, 256>>>(edge_feats, dst, We, be, out2);
    edge_gemm2_kernel<<<ge, 256>>>(edge_feats, src, dst, Weu + 256*DIM, out2);
    // pooling + node update + graph update + broadcast
    pool_kernel<<<(NNODE + 31)/32, 128>>>(graph_feats, n2g);
    nodeupd_kernel<<<gn, 256>>>(node_feats, n2g, Wnu + 128*DIM, out1);
    graph_kernel<<<NGRAPH, 128>>>(Wnu, bnu);
    out3_kernel<<<(NNODE*32 + 255)/256, 256>>>(graph_feats, n2g, out3);
}

// round 13
// speedup vs baseline: 1.4784x; 1.4333x over previous
#include <cuda_runtime.h>
#include <cuda_bf16.h>
#include <cstdint>

#define NNODE 50000
#define NEDGE 800000
#define DIM 128
#define NGRAPH 100
#define NEG_SLOPE 0.01f

// ---------------- scratch (device globals) ----------------
__device__ float g_h [NNODE*DIM];
__device__ float g_u [NNODE*DIM];
__device__ float g_A [NNODE*DIM];
__device__ float g_BC[NNODE*DIM];
__device__ float g_P [NNODE*DIM];
__device__ float g_hf[NNODE*DIM];
__device__ float g_deg[NNODE];
__device__ float g_poolN[NGRAPH*DIM];
__device__ float g_poolE[NGRAPH*DIM];
__device__ float g_poolG[NGRAPH*DIM];
__device__ float g_cntN[NGRAPH];
__device__ float g_cntE[NGRAPH];
__device__ float g_gnew[NGRAPH*DIM];
// prepacked bf16 weight fragments: [weight(0=We,1=Weu2)][hi/lo][8192 u32]
__device__ uint32_t g_Wp[2][2][8192];

__device__ __forceinline__ float lrelu(float x) { return x > 0.0f ? x : NEG_SLOPE * x; }

// ---------------- packed fp32x2 helpers (Blackwell FFMA2) ----------------
__device__ __forceinline__ void ffma2(unsigned long long& d,
                                      unsigned long long a,
                                      unsigned long long b)
{
    asm("fma.rn.f32x2 %0, %1, %2, %3;" : "=l"(d) : "l"(a), "l"(b), "l"(d));
}
__device__ __forceinline__ unsigned long long splat2(float x)
{
    unsigned long long r;
    asm("mov.b64 %0, {%1, %1};" : "=l"(r) : "f"(x));
    return r;
}
__device__ __forceinline__ float2 unpack2(unsigned long long v)
{
    float2 r;
    asm("mov.b64 {%0, %1}, %2;" : "=f"(r.x), "=f"(r.y) : "l"(v));
    return r;
}

// ---------------- mma.sync helpers (baseline PTX, sm_80+) ----------------
__device__ __forceinline__ uint32_t smem_u32(const void* p)
{
    uint32_t a;
    asm("{ .reg .u64 t; cvta.to.shared.u64 t, %1; cvt.u32.u64 %0, t; }" : "=r"(a) : "l"(p));
    return a;
}
__device__ __forceinline__ void ldmatrix_x4(uint32_t* r, uint32_t addr)
{
    asm volatile("ldmatrix.sync.aligned.m8n8.x4.shared.b16 {%0,%1,%2,%3}, [%4];"
                 : "=r"(r[0]), "=r"(r[1]), "=r"(r[2]), "=r"(r[3]) : "r"(addr));
}
__device__ __forceinline__ void mma_bf16(float* d, const uint32_t* a, uint32_t b0, uint32_t b1)
{
    asm volatile("mma.sync.aligned.m16n8k16.row.col.f32.bf16.bf16.f32 "
                 "{%0,%1,%2,%3}, {%4,%5,%6,%7}, {%8,%9}, {%0,%1,%2,%3};"
                 : "+f"(d[0]), "+f"(d[1]), "+f"(d[2]), "+f"(d[3])
                 : "r"(a[0]), "r"(a[1]), "r"(a[2]), "r"(a[3]), "r"(b0), "r"(b1));
}
__device__ __forceinline__ uint32_t bf16x2_hi(float x, float y, float& rx, float& ry)
{
    __nv_bfloat16 hx = __float2bfloat16(x), hy = __float2bfloat16(y);
    rx = x - __bfloat162float(hx);
    ry = y - __bfloat162float(hy);
    __nv_bfloat162 p; p.x = hx; p.y = hy;
    return *(uint32_t*)&p;
}
__device__ __forceinline__ uint32_t bf16x2_of(float x, float y)
{
    __nv_bfloat162 p; p.x = __float2bfloat16(x); p.y = __float2bfloat16(y);
    return *(uint32_t*)&p;
}

// ---------------- zero scratch accumulators ----------------
__global__ void zero_kernel()
{
    int i = blockIdx.x * blockDim.x + threadIdx.x;
    int stride = gridDim.x * blockDim.x;
    for (int k = i; k < NNODE*DIM; k += stride) g_hf[k] = 0.0f;
    for (int k = i; k < NNODE; k += stride) g_deg[k] = 0.0f;
    for (int k = i; k < NGRAPH*DIM; k += stride) { g_poolN[k]=0.f; g_poolE[k]=0.f; g_poolG[k]=0.f; }
    for (int k = i; k < NGRAPH; k += stride) { g_cntN[k]=0.f; g_cntE[k]=0.f; }
}

// ---------------- weight prepack into mma B-fragment order ----------------
// g_Wp[w][hl][((ks*8 + c)*32 + lane)*4 + j]:
//   nt = 2c + (j>>1), r = j&1; n = nt*8 + lane/4; k = ks*16 + (lane%4)*2 + r*8
//   value = bf16x2{ W[k][n], W[k+1][n] } (hi) / residual (lo)
__global__ void prepack_kernel(const float* __restrict__ We,
                               const float* __restrict__ Weu2)
{
    int idx = blockIdx.x * blockDim.x + threadIdx.x;
    if (idx >= 2*8192) return;
    int w  = idx >> 13;
    int r4 = idx & 8191;
    int j    = r4 & 3;
    int lane = (r4 >> 2) & 31;
    int cc   = (r4 >> 7) & 7;
    int ks   = (r4 >> 10) & 7;
    const float* W = w ? Weu2 : We;
    int n = (2*cc + (j >> 1))*8 + (lane >> 2);
    int k = ks*16 + (lane & 3)*2 + (j & 1)*8;
    float w0 = W[(size_t)k*DIM + n];
    float w1 = W[(size_t)(k+1)*DIM + n];
    __nv_bfloat16 h0 = __float2bfloat16(w0), h1 = __float2bfloat16(w1);
    float l0 = w0 - __bfloat162float(h0);
    float l1 = w1 - __bfloat162float(h1);
    __nv_bfloat162 ph; ph.x = h0; ph.y = h1;
    __nv_bfloat162 pl; pl.x = __float2bfloat16(l0); pl.y = __float2bfloat16(l1);
    g_Wp[w][0][r4] = *(uint32_t*)&ph;
    g_Wp[w][1][r4] = *(uint32_t*)&pl;
}

// ============================================================================
// Tensor-core edge GEMM: one 128-edge tile per block, 256 threads (8 warps,
// 4m x 2n warp grid, warp tile 32x64). K chunks of 32; bf16-split 3-MMA:
// D = Ahi@Bhi + Ahi@Blo + Alo@Bhi  (fp32 accum, err ~2^-18)
// MODE 0: f = lrelu(EF@We + be) -> out2
// MODE 1: t = f@Weu2 (f from out2); f_new = lrelu(t + A[src] + BC[dst]);
//         out2 = f_new + EF; g_hf[dst] += f_new
// ============================================================================
#define SA_STRIDE 80   // bytes per A row (32 bf16 = 64B, padded to 80 for banks)

template<int MODE>
__global__ __launch_bounds__(256) void mma_edge_kernel(
    const float* __restrict__ X,       // EF (MODE 0) or out2-f (MODE 1)
    const float* __restrict__ EF,
    const int* __restrict__ src,
    const int* __restrict__ dst,
    const float* __restrict__ be,
    float* __restrict__ out2)
{
    __shared__ __align__(16) unsigned char sA[2][128*SA_STRIDE]; // hi, lo (20480B)
    __shared__ __align__(16) uint32_t sB[2][2048];               // hi, lo (16384B)
    __shared__ float sbe[128];
    __shared__ int   sidx[256];

    const int tid = threadIdx.x;
    const int l = tid & 31;
    const int wid = tid >> 5;
    const int warpM = wid >> 1;      // 0..3
    const int warpN = wid & 1;       // 0..1
    const int m0 = blockIdx.x * 128;

    if (MODE == 0) {
        if (tid < 128) {
            sbe[tid] = be[tid];
            atomicAdd(&g_deg[dst[m0 + tid]], 1.0f);
        }
    } else {
        if (tid < 128) {
            sidx[tid]       = src[m0 + tid];
            sidx[128 + tid] = dst[m0 + tid];
        }
    }

    float acc[2][8][4];
    #pragma unroll
    for (int mt = 0; mt < 2; mt++)
        #pragma unroll
        for (int nt = 0; nt < 8; nt++)
            #pragma unroll
            for (int q = 0; q < 4; q++) acc[mt][nt][q] = 0.0f;

    const uint32_t sAhi_a = smem_u32(sA[0]);
    const uint32_t sAlo_a = smem_u32(sA[1]);
    const uint32_t* WpHi = g_Wp[MODE][0];
    const uint32_t* WpLo = g_Wp[MODE][1];

    const int arow  = tid >> 1;      // 0..127
    const int ahalf = tid & 1;
    const float* Xrow = X + (size_t)(m0 + arow)*DIM;

    for (int ch = 0; ch < 4; ch++) {
        // ---- stage A chunk (fp32 -> bf16 hi/lo) ----
        {
            const float* p = Xrow + ch*32 + ahalf*16;
            unsigned char* bhi = sA[0] + arow*SA_STRIDE + ahalf*32;
            unsigned char* blo = sA[1] + arow*SA_STRIDE + ahalf*32;
            #pragma unroll
            for (int j2 = 0; j2 < 4; j2++) {
                float4 v = *(const float4*)(p + j2*4);
                float rx, ry, rz, rw;
                uint32_t h0 = bf16x2_hi(v.x, v.y, rx, ry);
                uint32_t h1 = bf16x2_hi(v.z, v.w, rz, rw);
                *(uint2*)(bhi + j2*8) = make_uint2(h0, h1);
                *(uint2*)(blo + j2*8) = make_uint2(bf16x2_of(rx, ry), bf16x2_of(rz, rw));
            }
        }
        // ---- stage B chunk (prepacked fragments, verbatim copy) ----
        #pragma unroll
        for (int j2 = 0; j2 < 2; j2++) {
            *(uint4*)&sB[0][j2*1024 + tid*4] = *(const uint4*)(WpHi + ch*2048 + j2*1024 + tid*4);
            *(uint4*)&sB[1][j2*1024 + tid*4] = *(const uint4*)(WpLo + ch*2048 + j2*1024 + tid*4);
        }
        __syncthreads();

        #pragma unroll
        for (int ks = 0; ks < 2; ks++) {
            uint32_t ah[2][4], al[2][4];
            #pragma unroll
            for (int mt = 0; mt < 2; mt++) {
                uint32_t rowb = (uint32_t)(warpM*32 + mt*16 + (l & 15));
                uint32_t coff = ((uint32_t)(l >> 4))*16 + (uint32_t)ks*32;
                ldmatrix_x4(ah[mt], sAhi_a + rowb*SA_STRIDE + coff);
                ldmatrix_x4(al[mt], sAlo_a + rowb*SA_STRIDE + coff);
            }
            #pragma unroll
            for (int c2 = 0; c2 < 4; c2++) {
                int cgl = warpN*4 + c2;
                int bidx = ((ks*8 + cgl)*32 + l)*4;
                uint4 bh = *(const uint4*)&sB[0][bidx];
                uint4 bl = *(const uint4*)&sB[1][bidx];
                #pragma unroll
                for (int mt = 0; mt < 2; mt++) {
                    mma_bf16(acc[mt][c2*2+0], ah[mt], bh.x, bh.y);
                    mma_bf16(acc[mt][c2*2+0], ah[mt], bl.x, bl.y);
                    mma_bf16(acc[mt][c2*2+0], al[mt], bh.x, bh.y);
                    mma_bf16(acc[mt][c2*2+1], ah[mt], bh.z, bh.w);
                    mma_bf16(acc[mt][c2*2+1], ah[mt], bl.z, bl.w);
                    mma_bf16(acc[mt][c2*2+1], al[mt], bh.z, bh.w);
                }
            }
        }
        __syncthreads();
    }

    // ---- epilogue ----
    const int g  = l >> 2;
    const int tg = l & 3;
    #pragma unroll
    for (int mt = 0; mt < 2; mt++) {
        int rloc = warpM*32 + mt*16 + g;
        int e0 = m0 + rloc;
        int e1 = e0 + 8;
        if (MODE == 0) {
            #pragma unroll
            for (int nt = 0; nt < 8; nt++) {
                int c = warpN*64 + nt*8 + tg*2;
                float b0 = sbe[c], b1 = sbe[c+1];
                *(float2*)(out2 + (size_t)e0*DIM + c) =
                    make_float2(lrelu(acc[mt][nt][0] + b0), lrelu(acc[mt][nt][1] + b1));
                *(float2*)(out2 + (size_t)e1*DIM + c) =
                    make_float2(lrelu(acc[mt][nt][2] + b0), lrelu(acc[mt][nt][3] + b1));
            }
        } else {
            int s0 = sidx[rloc],     d0i = sidx[128 + rloc];
            int s1 = sidx[rloc + 8], d1i = sidx[128 + rloc + 8];
            #pragma unroll
            for (int nt = 0; nt < 8; nt++) {
                int c = warpN*64 + nt*8 + tg*2;
                float2 a0  = *(const float2*)(g_A  + (size_t)s0 *DIM + c);
                float2 bc0 = *(const float2*)(g_BC + (size_t)d0i*DIM + c);
                float2 ef0 = *(const float2*)(EF   + (size_t)e0 *DIM + c);
                float f00 = lrelu(acc[mt][nt][0] + a0.x + bc0.x);
                float f01 = lrelu(acc[mt][nt][1] + a0.y + bc0.y);
                *(float2*)(out2 + (size_t)e0*DIM + c) = make_float2(f00 + ef0.x, f01 + ef0.y);
                atomicAdd(g_hf + (size_t)d0i*DIM + c,     f00);
                atomicAdd(g_hf + (size_t)d0i*DIM + c + 1, f01);

                float2 a1  = *(const float2*)(g_A  + (size_t)s1 *DIM + c);
                float2 bc1 = *(const float2*)(g_BC + (size_t)d1i*DIM + c);
                float2 ef1 = *(const float2*)(EF   + (size_t)e1 *DIM + c);
                float f10 = lrelu(acc[mt][nt][2] + a1.x + bc1.x);
                float f11 = lrelu(acc[mt][nt][3] + a1.y + bc1.y);
                *(float2*)(out2 + (size_t)e1*DIM + c) = make_float2(f10 + ef1.x, f11 + ef1.y);
                atomicAdd(g_hf + (size_t)d1i*DIM + c,     f10);
                atomicAdd(g_hf + (size_t)d1i*DIM + c + 1, f11);
            }
        }
    }
}

// ============================================================================
// FFMA2 SIMT GEMM core (node-side; proven R9 code)
// ============================================================================
template<bool TWO, bool ACT, bool HASBIAS>
__device__ __forceinline__ void gemm128_core(
    const float* __restrict__ X0, const float* __restrict__ W0,
    const float* __restrict__ X1, const float* __restrict__ W1,
    const float* __restrict__ bias, float* __restrict__ out, int M)
{
    __shared__ __align__(16) float As0[16][132];
    __shared__ __align__(16) float Bs0[16][128];
    __shared__ __align__(16) float As1[TWO ? 16 : 1][TWO ? 132 : 1];
    __shared__ __align__(16) float Bs1[TWO ? 16 : 1][TWO ? 128 : 1];

    const int tid = threadIdx.x;
    const int tx = tid & 15, ty = tid >> 4;
    const int m0 = blockIdx.x * 128;

    const int lr  = tid >> 2;
    const int lk  = (tid & 3) * 4;
    const int bn4 = (tid & 31) * 4;
    const int bk  = tid >> 5;

    unsigned long long acc2[8][4];
    #pragma unroll
    for (int i = 0; i < 8; i++)
        #pragma unroll
        for (int j = 0; j < 4; j++) acc2[i][j] = 0ULL;

    for (int k0 = 0; k0 < DIM; k0 += 16) {
        #pragma unroll
        for (int it = 0; it < 2; it++) {
            int rr = lr + it*64;
            int row = min(m0 + rr, M - 1);
            float4 v = *(const float4*)(X0 + (size_t)row*DIM + k0 + lk);
            As0[lk+0][rr]=v.x; As0[lk+1][rr]=v.y; As0[lk+2][rr]=v.z; As0[lk+3][rr]=v.w;
            if (TWO) {
                float4 w = *(const float4*)(X1 + (size_t)row*DIM + k0 + lk);
                As1[lk+0][rr]=w.x; As1[lk+1][rr]=w.y; As1[lk+2][rr]=w.z; As1[lk+3][rr]=w.w;
            }
        }
        #pragma unroll
        for (int it = 0; it < 2; it++) {
            int kr = bk + it*8;
            *(float4*)&Bs0[kr][bn4] = *(const float4*)(W0 + (size_t)(k0+kr)*DIM + bn4);
            if (TWO)
                *(float4*)&Bs1[kr][bn4] = *(const float4*)(W1 + (size_t)(k0+kr)*DIM + bn4);
        }
        __syncthreads();
        #pragma unroll
        for (int kk = 0; kk < 16; kk++) {
            {
                float a[8];
                *(float4*)(a)   = *(float4*)&As0[kk][ty*8];
                *(float4*)(a+4) = *(float4*)&As0[kk][ty*8+4];
                ulonglong2 bA = *(ulonglong2*)&Bs0[kk][tx*8];
                ulonglong2 bB = *(ulonglong2*)&Bs0[kk][tx*8+4];
                unsigned long long b2[4] = {bA.x, bA.y, bB.x, bB.y};
                #pragma unroll
                for (int i = 0; i < 8; i++) {
                    unsigned long long a2 = splat2(a[i]);
                    ffma2(acc2[i][0], a2, b2[0]);
                    ffma2(acc2[i][1], a2, b2[1]);
                    ffma2(acc2[i][2], a2, b2[2]);
                    ffma2(acc2[i][3], a2, b2[3]);
                }
            }
            if (TWO) {
                float a[8];
                *(float4*)(a)   = *(float4*)&As1[kk][ty*8];
                *(float4*)(a+4) = *(float4*)&As1[kk][ty*8+4];
                ulonglong2 bA = *(ulonglong2*)&Bs1[kk][tx*8];
                ulonglong2 bB = *(ulonglong2*)&Bs1[kk][tx*8+4];
                unsigned long long b2[4] = {bA.x, bA.y, bB.x, bB.y};
                #pragma unroll
                for (int i = 0; i < 8; i++) {
                    unsigned long long a2 = splat2(a[i]);
                    ffma2(acc2[i][0], a2, b2[0]);
                    ffma2(acc2[i][1], a2, b2[1]);
                    ffma2(acc2[i][2], a2, b2[2]);
                    ffma2(acc2[i][3], a2, b2[3]);
                }
            }
        }
        __syncthreads();
    }

    float bv[8];
    if (HASBIAS) {
        *(float4*)(bv)   = *(const float4*)(bias + tx*8);
        *(float4*)(bv+4) = *(const float4*)(bias + tx*8 + 4);
    } else {
        #pragma unroll
        for (int j = 0; j < 8; j++) bv[j] = 0.0f;
    }

    #pragma unroll
    for (int i = 0; i < 8; i++) {
        int row = m0 + ty*8 + i;
        if (row >= M) continue;
        #pragma unroll
        for (int j4 = 0; j4 < 8; j4 += 4) {
            float2 p0 = unpack2(acc2[i][j4/2]);
            float2 p1 = unpack2(acc2[i][j4/2 + 1]);
            float v0 = p0.x + bv[j4+0];
            float v1 = p0.y + bv[j4+1];
            float v2 = p1.x + bv[j4+2];
            float v3 = p1.y + bv[j4+3];
            if (ACT) { v0 = lrelu(v0); v1 = lrelu(v1); v2 = lrelu(v2); v3 = lrelu(v3); }
            *(float4*)(out + (size_t)row*DIM + tx*8 + j4) = make_float4(v0, v1, v2, v3);
        }
    }
}

__global__ __launch_bounds__(256) void k_proj_h(const float* __restrict__ NF,
                                                const float* __restrict__ Wn,
                                                const float* __restrict__ bn)
{ gemm128_core<false, true, true>(NF, Wn, nullptr, nullptr, bn, g_h, NNODE); }

__global__ __launch_bounds__(256) void k_proj_u(const float* __restrict__ GF,
                                                const float* __restrict__ Wg,
                                                const float* __restrict__ bg)
{ gemm128_core<false, true, true>(GF, Wg, nullptr, nullptr, bg, g_u, NNODE); }

__global__ __launch_bounds__(256) void k_pre_A(const float* __restrict__ Weu0)
{ gemm128_core<false, false, false>(g_h, Weu0, nullptr, nullptr, nullptr, g_A, NNODE); }

__global__ __launch_bounds__(256) void k_pre_BC(const float* __restrict__ Weu1,
                                                const float* __restrict__ Weu3,
                                                const float* __restrict__ beu)
{ gemm128_core<true, false, true>(g_h, Weu1, g_u, Weu3, beu, g_BC, NNODE); }

__global__ __launch_bounds__(256) void k_pre_P(const float* __restrict__ Wnu0,
                                               const float* __restrict__ Wnu2,
                                               const float* __restrict__ bnu)
{ gemm128_core<true, false, true>(g_h, Wnu0, g_u, Wnu2, bnu, g_P, NNODE); }

// ============================================================================
// Node update (FFMA2) + node pool
// ============================================================================
__global__ __launch_bounds__(256) void nodeupd_kernel(
    const float* __restrict__ NF,
    const int* __restrict__ n2g,
    const float* __restrict__ Wnu1,
    float* __restrict__ out1)
{
    __shared__ __align__(16) float As[16][132];
    __shared__ __align__(16) float Bs[16][128];
    __shared__ float sinv[128];
    __shared__ int   sg[128];

    const int tid = threadIdx.x;
    const int tx = tid & 15, ty = tid >> 4;
    const int m0 = blockIdx.x * 128;

    if (tid < 128) {
        int r = min(m0 + tid, NNODE - 1);
        sinv[tid] = 1.0f / fmaxf(g_deg[r], 1.0f);
        sg[tid]   = n2g[r];
    }
    __syncthreads();

    const int lr  = tid >> 2;
    const int lk  = (tid & 3) * 4;
    const int bn4 = (tid & 31) * 4;
    const int bk  = tid >> 5;

    unsigned long long acc2[8][4];
    #pragma unroll
    for (int i = 0; i < 8; i++)
        #pragma unroll
        for (int j = 0; j < 4; j++) acc2[i][j] = 0ULL;

    for (int k0 = 0; k0 < DIM; k0 += 16) {
        #pragma unroll
        for (int it = 0; it < 2; it++) {
            int rr = lr + it*64;
            int row = min(m0 + rr, NNODE - 1);
            float sc = sinv[rr];
            float4 v = *(const float4*)(g_hf + (size_t)row*DIM + k0 + lk);
            As[lk+0][rr]=v.x*sc; As[lk+1][rr]=v.y*sc; As[lk+2][rr]=v.z*sc; As[lk+3][rr]=v.w*sc;
        }
        #pragma unroll
        for (int it = 0; it < 2; it++) {
            int kr = bk + it*8;
            *(float4*)&Bs[kr][bn4] = *(const float4*)(Wnu1 + (size_t)(k0+kr)*DIM + bn4);
        }
        __syncthreads();
        #pragma unroll
        for (int kk = 0; kk < 16; kk++) {
            float a[8];
            *(float4*)(a)   = *(float4*)&As[kk][ty*8];
            *(float4*)(a+4) = *(float4*)&As[kk][ty*8+4];
            ulonglong2 bA = *(ulonglong2*)&Bs[kk][tx*8];
            ulonglong2 bB = *(ulonglong2*)&Bs[kk][tx*8+4];
            unsigned long long b2[4] = {bA.x, bA.y, bB.x, bB.y};
            #pragma unroll
            for (int i = 0; i < 8; i++) {
                unsigned long long a2 = splat2(a[i]);
                ffma2(acc2[i][0], a2, b2[0]);
                ffma2(acc2[i][1], a2, b2[1]);
                ffma2(acc2[i][2], a2, b2[2]);
                ffma2(acc2[i][3], a2, b2[3]);
            }
        }
        __syncthreads();
    }

    float accf[8][8];
    #pragma unroll
    for (int i = 0; i < 8; i++) {
        int row = m0 + ty*8 + i;
        int rc = min(row, NNODE - 1);
        const float* Pr = g_P + (size_t)rc*DIM + tx*8;
        const float* Nr = NF  + (size_t)rc*DIM + tx*8;
        #pragma unroll
        for (int j4 = 0; j4 < 8; j4 += 4) {
            float2 p0 = unpack2(acc2[i][j4/2]);
            float2 p1 = unpack2(acc2[i][j4/2 + 1]);
            float4 pp = *(const float4*)(Pr + j4);
            float4 n4 = *(const float4*)(Nr + j4);
            accf[i][j4+0] = lrelu(p0.x + pp.x);
            accf[i][j4+1] = lrelu(p0.y + pp.y);
            accf[i][j4+2] = lrelu(p1.x + pp.z);
            accf[i][j4+3] = lrelu(p1.y + pp.w);
            if (row < NNODE) {
                *(float4*)(out1 + (size_t)row*DIM + tx*8 + j4) =
                    make_float4(accf[i][j4+0]+n4.x, accf[i][j4+1]+n4.y,
                                accf[i][j4+2]+n4.z, accf[i][j4+3]+n4.w);
            }
        }
    }

    #pragma unroll
    for (int j = 0; j < 8; j++) {
        float run = 0.0f;
        int curg = sg[ty*8];
        #pragma unroll
        for (int i = 0; i < 8; i++) {
            int row = m0 + ty*8 + i;
            int gg = sg[ty*8 + i];
            if (gg != curg) {
                atomicAdd(&g_poolN[curg*DIM + tx*8 + j], run);
                run = 0.0f; curg = gg;
            }
            if (row < NNODE) run += accf[i][j];
        }
        atomicAdd(&g_poolN[curg*DIM + tx*8 + j], run);
    }
}

// ---------------- pools over nodes ----------------
__global__ void pool_kernel(const float* __restrict__ GF, const int* __restrict__ n2g)
{
    const int c  = threadIdx.x;
    const int r0 = blockIdx.x * 32;
    float accE = 0.0f, accG = 0.0f, ccN = 0.0f, ccE = 0.0f;
    int curg = -1;
    int rend = min(r0 + 32, NNODE);
    for (int r = r0; r < rend; r++) {
        int gg = n2g[r];
        if (gg != curg) {
            if (curg >= 0) {
                atomicAdd(&g_poolE[curg*DIM + c], accE);
                atomicAdd(&g_poolG[curg*DIM + c], accG);
                if (c == 0) { atomicAdd(&g_cntN[curg], ccN); atomicAdd(&g_cntE[curg], ccE); }
            }
            accE = accG = ccN = ccE = 0.0f;
            curg = gg;
        }
        accE += g_hf[(size_t)r*DIM + c];
        accG += GF  [(size_t)r*DIM + c];
        if (c == 0) { ccN += 1.0f; ccE += g_deg[r]; }
    }
    if (curg >= 0) {
        atomicAdd(&g_poolE[curg*DIM + c], accE);
        atomicAdd(&g_poolG[curg*DIM + c], accG);
        if (c == 0) { atomicAdd(&g_cntN[curg], ccN); atomicAdd(&g_cntE[curg], ccE); }
    }
}

// ---------------- graph update ----------------
__global__ void graph_kernel(const float* __restrict__ Wnu, const float* __restrict__ bnu)
{
    __shared__ float sc[384];
    const int g = blockIdx.x;
    const int c = threadIdx.x;
    float nn = fmaxf(g_cntN[g], 1.0f);
    float ne = fmaxf(g_cntE[g], 1.0f);
    sc[c]       = g_poolN[g*DIM + c] / nn;
    sc[128 + c] = g_poolE[g*DIM + c] / ne;
    sc[256 + c] = g_poolG[g*DIM + c] / nn;
    __syncthreads();
    float acc = bnu[c];
    #pragma unroll 8
    for (int k = 0; k < 384; k++) acc += sc[k] * Wnu[(size_t)k*DIM + c];
    g_gnew[g*DIM + c] = lrelu(acc);
}

// ---------------- out3 = g_new[node2graph] + graph_feats ----------------
__global__ void out3_kernel(const float* __restrict__ GF, const int* __restrict__ n2g,
                            float* __restrict__ out3)
{
    int idx = blockIdx.x * blockDim.x + threadIdx.x;
    if (idx >= NNODE * 32) return;
    int node = idx >> 5;
    int c4 = (idx & 31) * 4;
    float4 gv = *(const float4*)(g_gnew + (size_t)n2g[node]*DIM + c4);
    float4 gf = *(const float4*)(GF + (size_t)node*DIM + c4);
    *(float4*)(out3 + (size_t)node*DIM + c4) =
        make_float4(gv.x+gf.x, gv.y+gf.y, gv.z+gf.z, gv.w+gf.w);
}

// ---------------- launch: pure kernel launches, no host CUDA API ----------------
extern "C" void kernel_launch(void* const* d_in, const int* in_sizes, int n_in,
                              void* d_out, int out_size)
{
    const float* node_feats  = (const float*)d_in[0];
    const float* edge_feats  = (const float*)d_in[1];
    const float* graph_feats = (const float*)d_in[2];
    const int*   src = (const int*)d_in[3];
    const int*   dst = (const int*)d_in[4];
    const int*   n2g = (const int*)d_in[5];
    const float* Wn  = (const float*)d_in[6];
    const float* bn  = (const float*)d_in[7];
    const float* We  = (const float*)d_in[8];
    const float* be  = (const float*)d_in[9];
    const float* Wg  = (const float*)d_in[10];
    const float* bg  = (const float*)d_in[11];
    const float* Weu = (const float*)d_in[12];
    const float* beu = (const float*)d_in[13];
    const float* Wnu = (const float*)d_in[14];
    const float* bnu = (const float*)d_in[15];

    float* out  = (float*)d_out;
    float* out1 = out;
    float* out2 = out + (size_t)NNODE*DIM;
    float* out3 = out + (size_t)NNODE*DIM + (size_t)NEDGE*DIM;

    const int gn = (NNODE + 127) / 128;
    const int ge = NEDGE / 128;

    zero_kernel<<<512, 256>>>();
    prepack_kernel<<<(2*8192 + 255)/256, 256>>>(We, Weu + 256*DIM);
    // projections + per-node precomputations (FFMA2)
    k_proj_h<<<gn, 256>>>(node_feats, Wn, bn);
    k_proj_u<<<gn, 256>>>(graph_feats, Wg, bg);
    k_pre_A <<<gn, 256>>>(Weu);
    k_pre_BC<<<gn, 256>>>(Weu + 128*DIM, Weu + 384*DIM, beu);
    k_pre_P <<<gn, 256>>>(Wnu, Wnu + 256*DIM, bnu);
    // edge pipeline on tensor cores (f staged in out2)
    mma_edge_kernel<0><<<ge, 256>>>(edge_feats, edge_feats, src, dst, be, out2);
    mma_edge_kernel<1><<<ge, 256>>>(out2, edge_feats, src, dst, be, out2);
    // pooling + node update + graph update + broadcast
    pool_kernel<<<(NNODE + 31)/32, 128>>>(graph_feats, n2g);
    nodeupd_kernel<<<gn, 256>>>(node_feats, n2g, Wnu + 128*DIM, out1);
    graph_kernel<<<NGRAPH, 128>>>(Wnu, bnu);
    out3_kernel<<<(NNODE*32 + 255)/256, 256>>>(graph_feats, n2g, out3);
}